// round 13
// baseline (speedup 1.0000x reference)
#include <cuda_runtime.h>
#include <cuda_bf16.h>
#include <cstdint>

#define NB  16
#define SEQ 2048
#define DKH 64
#define KSTR 68     // sK/sP row stride (words)
#define VSTR 72     // sV row stride (words)
#define SC2  0.18033688f   // 0.125 * log2(e)

// ---------------- device scratch ----------------
__device__ uint32_t g_Qt[NB * SEQ * DKH];            // tf32 bits
__device__ uint32_t g_Kt[NB * SEQ * DKH];
__device__ uint32_t g_Vt[NB * SEQ * DKH];
__device__ uint32_t g_Pt[SEQ * DKH];                 // transposed Krelpos, tf32
__device__ __nv_bfloat16 g_QPb[(size_t)NB * SEQ * SEQ];  // shifted bias*SC2 [b][s][t]
__device__ float g_O0[(size_t)NB * SEQ * DKH];
__device__ float g_O1[(size_t)NB * SEQ * DKH];
__device__ float g_l0[NB * SEQ];
__device__ float g_l1[NB * SEQ];
__device__ int g_ctrA;                               // attn work counter
__device__ int g_ctrB;                               // bias work counter

// ---------------- helpers ----------------
__device__ __forceinline__ float f2tf(float x) {
    uint32_t u; asm("cvt.rna.tf32.f32 %0, %1;" : "=r"(u) : "f"(x));
    return __uint_as_float(u);
}
__device__ __forceinline__ uint32_t fu(float x) { return __float_as_uint(x); }
__device__ __forceinline__ uint32_t smem_u32(const void* p) {
    uint32_t a;
    asm("{ .reg .u64 t; cvta.to.shared.u64 t, %1; cvt.u32.u64 %0, t; }" : "=r"(a) : "l"(p));
    return a;
}
__device__ __forceinline__ void mma_tf32(float d[4], const uint32_t a[4], const uint32_t b[2]) {
    asm volatile("mma.sync.aligned.m16n8k8.row.col.f32.tf32.tf32.f32 "
        "{%0,%1,%2,%3}, {%4,%5,%6,%7}, {%8,%9}, {%0,%1,%2,%3};"
        : "+f"(d[0]), "+f"(d[1]), "+f"(d[2]), "+f"(d[3])
        : "r"(a[0]), "r"(a[1]), "r"(a[2]), "r"(a[3]), "r"(b[0]), "r"(b[1]));
}
__device__ __forceinline__ void cpa16(uint32_t s, const void* g) {
    asm volatile("cp.async.cg.shared.global [%0], [%1], 16;" :: "r"(s), "l"(g));
}
#define CP_COMMIT() asm volatile("cp.async.commit_group;")
#define CP_WAIT(n)  asm volatile("cp.async.wait_group %0;" :: "n"(n) : "memory")

// 64x64 f32 sub-tile: gmem row-major -> padded smem
__device__ __forceinline__ void cp_sub(uint32_t sbase, const float* gsrc, int tid, int stride) {
#pragma unroll
    for (int k = 0; k < 4; k++) {
        int idx = k * 256 + tid;
        int row = idx >> 4, c4 = (idx & 15) * 4;
        cpa16(sbase + (uint32_t)(row * stride + c4) * 4u, gsrc + row * 64 + c4);
    }
}
// 128x64 tile
__device__ __forceinline__ void cp_tile(uint32_t sbase, const float* gsrc, int tid, int stride) {
#pragma unroll
    for (int k = 0; k < 8; k++) {
        int idx = k * 256 + tid;
        int row = idx >> 4, c4 = (idx & 15) * 4;
        cpa16(sbase + (uint32_t)(row * stride + c4) * 4u, gsrc + row * 64 + c4);
    }
}
// LPT work item decode: idx in [0,384) -> (qi, chunk, b, klo, khi)
__device__ __forceinline__ void decode_item(int idx, int& qi, int& ch, int& b,
                                            int& klo, int& khi) {
    if (idx < 256) { qi = 15 - (idx >> 5); ch = (idx >> 4) & 1; b = idx & 15; }
    else           { int t = idx - 256; qi = 7 - (t >> 4); ch = 0; b = t & 15; }
    klo = 0; khi = qi + 1;
    if (qi >= 8) { int h2 = (qi + 2) >> 1; if (ch) klo = h2; else khi = h2; }
}

// ---------------- prep ----------------
__global__ void prep_kernel(const float* __restrict__ Q, const float* __restrict__ K,
                            const float* __restrict__ V, const float* __restrict__ Kp) {
    int i = blockIdx.x * 256 + threadIdx.x;
    if (i == 0) { g_ctrA = 0; g_ctrB = 0; }
    if (i < NB * SEQ * DKH) {
        g_Qt[i] = fu(f2tf(Q[i]));
        g_Kt[i] = fu(f2tf(K[i]));
        g_Vt[i] = fu(f2tf(V[i]));
    }
    if (i < SEQ * DKH) {
        int c = i >> 6, d = i & 63;
        g_Pt[i] = fu(f2tf(Kp[d * SEQ + c]));
    }
}

// ---------------- bias GEMM (persistent): g_QPb[b][s][t] = SC2 * Q[b,s].Pt[2047-s+t]
#define BSMEM (2 * 128 * KSTR * 4)

__global__ void __launch_bounds__(256, 2) bias_kernel() {
    extern __shared__ float sm[];
    uint32_t smb = smem_u32(sm);
    const float* sQf = sm;
    const float* sBf = sm + 128 * KSTR;
    __shared__ int sWork;
    const int tid = threadIdx.x, w = tid >> 5, lane = tid & 31;
    const int g = lane >> 2, j = lane & 3;

    for (;;) {
        if (tid == 0) sWork = atomicAdd(&g_ctrB, 1);
        __syncthreads();
        const int idx = sWork;
        __syncthreads();
        if (idx >= 384) return;
        int si, ch, b, klo, khi;
        decode_item(idx, si, ch, b, klo, khi);

        // Q tile once per item
        cp_tile(smb, (const float*)g_Qt + ((size_t)(b * SEQ + si * 128)) * DKH, tid, KSTR);
        CP_COMMIT(); CP_WAIT(0);
        __syncthreads();

        uint32_t qa[8][4];
#pragma unroll
        for (int k8 = 0; k8 < 8; k8++) {
            const float* ap = sQf + (w * 16 + g) * KSTR + k8 * 8 + j;
            qa[k8][0] = fu(ap[0]);
            qa[k8][1] = fu(ap[8 * KSTR]);
            qa[k8][2] = fu(ap[4]);
            qa[k8][3] = fu(ap[8 * KSTR + 4]);
        }
        const int sr = si * 128 + w * 16 + g;
        __nv_bfloat16* row0 = g_QPb + ((size_t)(b * SEQ + sr)) * SEQ;
        __nv_bfloat16* row1 = row0 + (size_t)8 * SEQ;

        for (int kk = klo; kk < khi; kk++) {
            const int ci = 15 - si + kk;
            __syncthreads();        // prior sB reads done
            cp_tile(smb + 128 * KSTR * 4,
                    (const float*)g_Pt + (size_t)ci * 128 * DKH, tid, KSTR);
            CP_COMMIT(); CP_WAIT(0);
            __syncthreads();

            const int tb0 = ci * 128 + 2 * j + sr - 2047;
            const int tb1 = tb0 + 8;
#pragma unroll
            for (int n = 0; n < 16; n++) {
                float c[4] = {0.f, 0.f, 0.f, 0.f};
#pragma unroll
                for (int k8 = 0; k8 < 8; k8++) {
                    const float* bp = sBf + (n * 8 + g) * KSTR + k8 * 8 + j;
                    uint32_t bb[2] = {fu(bp[0]), fu(bp[4])};
                    mma_tf32(c, qa[k8], bb);
                }
                const int t0 = tb0 + n * 8;
                if (t0 >= 0)     row0[t0]     = __float2bfloat16_rn(c[0] * SC2);
                if (t0 + 1 >= 0) row0[t0 + 1] = __float2bfloat16_rn(c[1] * SC2);
                const int t1 = tb1 + n * 8;
                if (t1 >= 0)     row1[t1]     = __float2bfloat16_rn(c[2] * SC2);
                if (t1 + 1 >= 0) row1[t1 + 1] = __float2bfloat16_rn(c[3] * SC2);
            }
        }
    }
}

// ---------------- attention: persistent, split-K, double-buffered 64-key subtiles
#define ASMEM ((2 * 64 * KSTR + 2 * 64 * VSTR + 128 * KSTR) * 4)   // 106496

__global__ void __launch_bounds__(256, 2) attn_kernel() {
    extern __shared__ float sm[];
    const uint32_t smb = smem_u32(sm);
    // layout: sK[2] | sV[2] | sP
    const uint32_t sKb[2] = {smb, smb + 64 * KSTR * 4};
    const uint32_t sVb[2] = {smb + 2 * 64 * KSTR * 4, smb + (2 * 64 * KSTR + 64 * VSTR) * 4};
    const float* sKf[2] = {sm, sm + 64 * KSTR};
    const float* sVf[2] = {sm + 2 * 64 * KSTR, sm + 2 * 64 * KSTR + 64 * VSTR};
    float* sPf = sm + 2 * 64 * KSTR + 2 * 64 * VSTR;
    __shared__ int sWork;
    const int tid = threadIdx.x, w = tid >> 5, lane = tid & 31;
    const int g = lane >> 2, j = lane & 3;

    for (;;) {
        if (tid == 0) sWork = atomicAdd(&g_ctrA, 1);
        __syncthreads();
        const int idx = sWork;
        __syncthreads();
        if (idx >= 384) return;
        int qi, ch, b, klo, khi;
        decode_item(idx, qi, ch, b, klo, khi);
        const int sLo = 2 * klo, sHi = 2 * khi;      // 64-key subtile range

        const int s0 = qi * 128;
        const int r0 = w * 16 + g;
        const int rg = s0 + r0;

        // Q fragments straight from gmem (once per item)
        uint32_t qa[8][4];
        {
            const uint32_t* Qb = g_Qt + ((size_t)(b * SEQ + rg)) * DKH;
#pragma unroll
            for (int k8 = 0; k8 < 8; k8++) {
                qa[k8][0] = Qb[k8 * 8 + j];
                qa[k8][1] = Qb[8 * DKH + k8 * 8 + j];
                qa[k8][2] = Qb[k8 * 8 + j + 4];
                qa[k8][3] = Qb[8 * DKH + k8 * 8 + j + 4];
            }
        }

        float o[8][4];
#pragma unroll
        for (int n = 0; n < 8; n++) { o[n][0] = o[n][1] = o[n][2] = o[n][3] = 0.f; }
        float l0a = 0.f, l1a = 0.f;
        const __nv_bfloat16* bias0 = g_QPb + ((size_t)(b * SEQ + rg)) * SEQ;
        const __nv_bfloat16* bias1 = bias0 + (size_t)8 * SEQ;

        const float* Kt = (const float*)g_Kt + ((size_t)b * SEQ) * DKH;
        const float* Vt = (const float*)g_Vt + ((size_t)b * SEQ) * DKH;

        // pipeline prologue: load subtile sLo
        cp_sub(sKb[sLo & 1], Kt + (size_t)(sLo * 64) * DKH, tid, KSTR);
        cp_sub(sVb[sLo & 1], Vt + (size_t)(sLo * 64) * DKH, tid, VSTR);
        CP_COMMIT();

        for (int st = sLo; st < sHi; st++) {
            const int cur = st & 1;
            const int t0 = st * 64;
            const bool more = (st + 1 < sHi);
            if (more) {
                cp_sub(sKb[cur ^ 1], Kt + (size_t)((st + 1) * 64) * DKH, tid, KSTR);
                cp_sub(sVb[cur ^ 1], Vt + (size_t)((st + 1) * 64) * DKH, tid, VSTR);
                CP_COMMIT();
            }
            // bias prefetch (independent of smem)
            uint32_t bz0[8], bz1[8];
#pragma unroll
            for (int n8 = 0; n8 < 8; n8++) {
                const int col = t0 + n8 * 8 + 2 * j;
                bz0[n8] = *(const uint32_t*)(bias0 + col);
                bz1[n8] = *(const uint32_t*)(bias1 + col);
            }
            if (more) CP_WAIT(1); else CP_WAIT(0);
            __syncthreads();

            const bool diag = (st >= 2 * qi);        // subtile may cross diagonal
            const float* sK = sKf[cur];
            const float* sV = sVf[cur];

            // ---- S: 8 n-blocks over 64 keys -> exp -> sP
#pragma unroll
            for (int n8 = 0; n8 < 8; n8++) {
                float c[4] = {0.f, 0.f, 0.f, 0.f};
#pragma unroll
                for (int k8 = 0; k8 < 8; k8++) {
                    const float* bp = sK + (n8 * 8 + g) * KSTR + k8 * 8 + j;
                    uint32_t bb[2] = {fu(bp[0]), fu(bp[4])};
                    mma_tf32(c, qa[k8], bb);
                }
                const float b00 = __uint_as_float(bz0[n8] << 16);
                const float b01 = __uint_as_float(bz0[n8] & 0xFFFF0000u);
                const float b10 = __uint_as_float(bz1[n8] << 16);
                const float b11 = __uint_as_float(bz1[n8] & 0xFFFF0000u);
                float e0 = exp2f(fmaf(c[0], SC2, b00));
                float e1 = exp2f(fmaf(c[1], SC2, b01));
                float e2 = exp2f(fmaf(c[2], SC2, b10));
                float e3 = exp2f(fmaf(c[3], SC2, b11));
                if (diag) {
                    const int tc = t0 + n8 * 8 + 2 * j;
                    e0 = (tc     <= rg    ) ? e0 : 0.f;
                    e1 = (tc + 1 <= rg    ) ? e1 : 0.f;
                    e2 = (tc     <= rg + 8) ? e2 : 0.f;
                    e3 = (tc + 1 <= rg + 8) ? e3 : 0.f;
                }
                l0a += e0 + e1;
                l1a += e2 + e3;
                *(float2*)(sPf + r0 * KSTR + n8 * 8 + 2 * j) =
                    make_float2(f2tf(e0), f2tf(e1));
                *(float2*)(sPf + (r0 + 8) * KSTR + n8 * 8 + 2 * j) =
                    make_float2(f2tf(e2), f2tf(e3));
            }
            __syncthreads();       // sP ready

            // ---- PV: O += P(:,64) . V(64,:)
#pragma unroll
            for (int k8 = 0; k8 < 8; k8++) {
                const float* ap = sPf + r0 * KSTR + k8 * 8 + j;
                uint32_t aa[4] = {fu(ap[0]), fu(ap[8 * KSTR]),
                                  fu(ap[4]), fu(ap[8 * KSTR + 4])};
#pragma unroll
                for (int np = 0; np < 8; np++) {
                    const float* bp = sV + (k8 * 8 + j) * VSTR + np * 8 + g;
                    uint32_t bb[2] = {fu(bp[0]), fu(bp[4 * VSTR])};
                    mma_tf32(o[np], aa, bb);
                }
            }
            __syncthreads();       // sP + buffers reusable
        }

        l0a += __shfl_xor_sync(0xFFFFFFFFu, l0a, 1);
        l0a += __shfl_xor_sync(0xFFFFFFFFu, l0a, 2);
        l1a += __shfl_xor_sync(0xFFFFFFFFu, l1a, 1);
        l1a += __shfl_xor_sync(0xFFFFFFFFu, l1a, 2);

        float* Ob = (ch ? g_O1 : g_O0) + ((size_t)(b * SEQ + rg)) * DKH;
        float* lb = ch ? g_l1 : g_l0;
        if (j == 0) {
            lb[b * SEQ + rg] = l0a;
            lb[b * SEQ + rg + 8] = l1a;
        }
#pragma unroll
        for (int np = 0; np < 8; np++) {
            *(float2*)(Ob + np * 8 + 2 * j) = make_float2(o[np][0], o[np][1]);
            *(float2*)(Ob + 8 * DKH + np * 8 + 2 * j) = make_float2(o[np][2], o[np][3]);
        }
    }
}

// ---------------- final combine + normalize ----------------
__global__ void final_kernel(float* __restrict__ Out) {
    int i = blockIdx.x * 256 + threadIdx.x;
    int row = i >> 4;
    int c4 = (i & 15) * 4;
    int s = row & (SEQ - 1);
    float l = g_l0[row];
    float4 o = *(const float4*)(g_O0 + (size_t)row * DKH + c4);
    if (s >= 1024) {
        l += g_l1[row];
        float4 o1 = *(const float4*)(g_O1 + (size_t)row * DKH + c4);
        o.x += o1.x; o.y += o1.y; o.z += o1.z; o.w += o1.w;
    }
    const float inv = 1.0f / l;
    o.x *= inv; o.y *= inv; o.z *= inv; o.w *= inv;
    *(float4*)(Out + (size_t)row * DKH + c4) = o;
}

extern "C" void kernel_launch(void* const* d_in, const int* in_sizes, int n_in,
                              void* d_out, int out_size) {
    const float* Q  = (const float*)d_in[0];
    const float* K  = (const float*)d_in[1];
    const float* V  = (const float*)d_in[2];
    const float* Kp = (const float*)d_in[3];
    float* Out      = (float*)d_out;

    cudaFuncSetAttribute(bias_kernel, cudaFuncAttributeMaxDynamicSharedMemorySize, BSMEM);
    cudaFuncSetAttribute(attn_kernel, cudaFuncAttributeMaxDynamicSharedMemorySize, ASMEM);

    prep_kernel<<<(NB * SEQ * DKH + 255) / 256, 256>>>(Q, K, V, Kp);
    bias_kernel<<<296, 256, BSMEM>>>();
    attn_kernel<<<296, 256, ASMEM>>>();
    final_kernel<<<(NB * SEQ * DKH / 4 + 255) / 256, 256>>>(Out);
}